// round 1
// baseline (speedup 1.0000x reference)
#include <cuda_runtime.h>
#include <math.h>

#define Bn 64
#define Tn 2048
#define Dn 256
#define Un 256

// ---- scratch (device globals, no allocation) ----
__device__ float d_qp[Bn * Un];          // q_proj + W1_b + W2_b
__device__ float d_score[Bn * Tn];       // pre-softmax scores
__device__ float d_maxv[Bn];
__device__ float d_den[Bn];
__device__ float d_part[Bn * 8 * Dn];    // partial context sums

// ============================================================
// Kernel 1: q_proj[b][u] = query[b]@W1[:,u] + W1_b[u] + W2_b[u]
// ============================================================
__global__ void qproj_kernel(const float* __restrict__ query,
                             const float* __restrict__ W1w,
                             const float* __restrict__ W1b,
                             const float* __restrict__ W2b) {
    int b = blockIdx.x, u = threadIdx.x;
    __shared__ float qs[Dn];
    qs[u] = query[b * Dn + u];
    __syncthreads();
    float acc = 0.f;
#pragma unroll 8
    for (int d = 0; d < Dn; d++) acc = fmaf(qs[d], W1w[d * Un + u], acc);
    d_qp[b * Un + u] = acc + W1b[u] + W2b[u];
}

// ============================================================
// Kernel 2: fused GEMM + tanh + dot(V_w) -> scores
// Block = 64 rows (one b, 64 consecutive t) x full U=256.
// 256 threads, 8x8 micro-tile each, double-buffered smem, K-chunk=16.
// ============================================================
__global__ __launch_bounds__(256, 2)
void score_kernel(const float* __restrict__ values,
                  const float* __restrict__ W2w,
                  const float* __restrict__ Vw,
                  const float* __restrict__ Vb) {
    __shared__ __align__(16) float As[2][16 * 64];    // [k][m] (transposed)
    __shared__ __align__(16) float Bs[2][16 * 256];   // [k][u]
    __shared__ float qs[Un];
    __shared__ float vs[Un];

    const int tid = threadIdx.x;
    const int tx = tid & 31;          // 0..31 -> u groups
    const int ty = tid >> 5;          // 0..7  -> m groups
    const int r0 = blockIdx.x * 64;   // global row (b*T + t)
    const int b  = r0 >> 11;          // T = 2048

    qs[tid] = d_qp[b * Un + tid];
    vs[tid] = Vw[tid];

    // A global-load mapping: thread loads float4 of 4 consecutive d's for one row
    const int arow = tid >> 2;          // 0..63
    const int adq  = (tid & 3) << 2;    // 0,4,8,12
    const float* aptr = values + (size_t)(r0 + arow) * Dn + adq;

    float4 rA;
    float4 rB[4];

    // ---- prefetch kc = 0 into buffer 0 ----
    rA = *(const float4*)(aptr);
#pragma unroll
    for (int q = 0; q < 4; q++) {
        int k = q * 4 + (tid >> 6);
        int u = (tid & 63) << 2;
        rB[q] = *(const float4*)(W2w + k * Un + u);
    }
    // store A transposed: As[k][m]
    As[0][(adq + 0) * 64 + arow] = rA.x;
    As[0][(adq + 1) * 64 + arow] = rA.y;
    As[0][(adq + 2) * 64 + arow] = rA.z;
    As[0][(adq + 3) * 64 + arow] = rA.w;
#pragma unroll
    for (int q = 0; q < 4; q++) {
        int k = q * 4 + (tid >> 6);
        int u = (tid & 63) << 2;
        *(float4*)&Bs[0][k * 256 + u] = rB[q];
    }
    __syncthreads();

    float acc[2][2][4][4];
#pragma unroll
    for (int h = 0; h < 2; h++)
#pragma unroll
        for (int g = 0; g < 2; g++)
#pragma unroll
            for (int i = 0; i < 4; i++)
#pragma unroll
                for (int j = 0; j < 4; j++) acc[h][g][i][j] = 0.f;

    int cur = 0;
#pragma unroll 1
    for (int it = 0; it < 16; it++) {
        // prefetch next K-chunk while computing current
        if (it < 15) {
            int kc = (it + 1) * 16;
            rA = *(const float4*)(aptr + kc);
#pragma unroll
            for (int q = 0; q < 4; q++) {
                int k = q * 4 + (tid >> 6);
                int u = (tid & 63) << 2;
                rB[q] = *(const float4*)(W2w + (kc + k) * Un + u);
            }
        }
        // compute 16 k-steps from smem
#pragma unroll
        for (int k = 0; k < 16; k++) {
            float4 a0 = *(const float4*)&As[cur][k * 64 + ty * 4];        // rows ty*4..+3 (broadcast)
            float4 a1 = *(const float4*)&As[cur][k * 64 + 32 + ty * 4];   // rows 32+ty*4..
            float4 b0 = *(const float4*)&Bs[cur][k * 256 + tx * 4];       // cols tx*4..
            float4 b1 = *(const float4*)&Bs[cur][k * 256 + 128 + tx * 4]; // cols 128+tx*4..
            float av[2][4] = {{a0.x, a0.y, a0.z, a0.w}, {a1.x, a1.y, a1.z, a1.w}};
            float bv[2][4] = {{b0.x, b0.y, b0.z, b0.w}, {b1.x, b1.y, b1.z, b1.w}};
#pragma unroll
            for (int h = 0; h < 2; h++)
#pragma unroll
                for (int g = 0; g < 2; g++)
#pragma unroll
                    for (int i = 0; i < 4; i++)
#pragma unroll
                        for (int j = 0; j < 4; j++)
                            acc[h][g][i][j] = fmaf(av[h][i], bv[g][j], acc[h][g][i][j]);
        }
        if (it < 15) {
            int nxt = cur ^ 1;
            As[nxt][(adq + 0) * 64 + arow] = rA.x;
            As[nxt][(adq + 1) * 64 + arow] = rA.y;
            As[nxt][(adq + 2) * 64 + arow] = rA.z;
            As[nxt][(adq + 3) * 64 + arow] = rA.w;
#pragma unroll
            for (int q = 0; q < 4; q++) {
                int k = q * 4 + (tid >> 6);
                int u = (tid & 63) << 2;
                *(float4*)&Bs[nxt][k * 256 + u] = rB[q];
            }
            __syncthreads();
            cur = nxt;
        }
    }

    // ---- fused epilogue: score = sum_u tanh(acc + q_proj[u]) * Vw[u] ----
    float p[2][4];
#pragma unroll
    for (int h = 0; h < 2; h++)
#pragma unroll
        for (int i = 0; i < 4; i++) p[h][i] = 0.f;

#pragma unroll
    for (int g = 0; g < 2; g++)
#pragma unroll
        for (int j = 0; j < 4; j++) {
            int u = g * 128 + tx * 4 + j;
            float qv = qs[u];
            float vv = vs[u];
#pragma unroll
            for (int h = 0; h < 2; h++)
#pragma unroll
                for (int i = 0; i < 4; i++)
                    p[h][i] += tanhf(acc[h][g][i][j] + qv) * vv;
        }

    // reduce across the 32 u-lanes of each warp (warp = fixed ty = fixed rows)
#pragma unroll
    for (int off = 16; off > 0; off >>= 1)
#pragma unroll
        for (int h = 0; h < 2; h++)
#pragma unroll
            for (int i = 0; i < 4; i++)
                p[h][i] += __shfl_xor_sync(0xffffffffu, p[h][i], off);

    if (tx == 0) {
        float vb = Vb[0];
#pragma unroll
        for (int h = 0; h < 2; h++)
#pragma unroll
            for (int i = 0; i < 4; i++) {
                int m = h * 32 + ty * 4 + i;
                d_score[r0 + m] = p[h][i] + vb;
            }
    }
}

// ============================================================
// Kernel 3: per-b softmax stats (max, sum of exp)
// ============================================================
__device__ __forceinline__ float warp_max(float v) {
#pragma unroll
    for (int o = 16; o > 0; o >>= 1) v = fmaxf(v, __shfl_xor_sync(0xffffffffu, v, o));
    return v;
}
__device__ __forceinline__ float warp_sum(float v) {
#pragma unroll
    for (int o = 16; o > 0; o >>= 1) v += __shfl_xor_sync(0xffffffffu, v, o);
    return v;
}

__global__ void softmax_stats_kernel() {
    int b = blockIdx.x, tid = threadIdx.x;
    __shared__ float red[8];
    __shared__ float bc;

    float m = -1e30f;
    for (int t = tid; t < Tn; t += 256) m = fmaxf(m, d_score[b * Tn + t]);
    m = warp_max(m);
    if ((tid & 31) == 0) red[tid >> 5] = m;
    __syncthreads();
    if (tid < 32) {
        float v = (tid < 8) ? red[tid] : -1e30f;
        v = warp_max(v);
        if (tid == 0) bc = v;
    }
    __syncthreads();
    float mv = bc;

    float s = 0.f;
    for (int t = tid; t < Tn; t += 256) s += expf(d_score[b * Tn + t] - mv);
    s = warp_sum(s);
    if ((tid & 31) == 0) red[tid >> 5] = s;
    __syncthreads();
    if (tid < 32) {
        float v = (tid < 8) ? red[tid] : 0.f;
        v = warp_sum(v);
        if (tid == 0) { d_maxv[b] = mv; d_den[b] = v; }
    }
}

// ============================================================
// Kernel 4: weights + partial context (grid = B*8, chunk of 256 t's)
// ============================================================
__global__ void weights_ctx_kernel(const float* __restrict__ values,
                                   float* __restrict__ out) {
    int b = blockIdx.x >> 3;
    int ch = blockIdx.x & 7;
    int tid = threadIdx.x;
    __shared__ float sw[256];

    int t = ch * 256 + tid;
    float w = expf(d_score[b * Tn + t] - d_maxv[b]) / d_den[b];
    out[Bn * Dn + b * Tn + t] = w;   // attention_weights region
    sw[tid] = w;
    __syncthreads();

    float acc = 0.f;
    const float* vp = values + ((size_t)(b * Tn + ch * 256)) * Dn + tid;
#pragma unroll 4
    for (int tt = 0; tt < 256; tt++) acc = fmaf(sw[tt], vp[(size_t)tt * Dn], acc);
    d_part[(b * 8 + ch) * Dn + tid] = acc;
}

// ============================================================
// Kernel 5: reduce partial contexts -> context_vector
// ============================================================
__global__ void reduce_ctx_kernel(float* __restrict__ out) {
    int b = blockIdx.x, d = threadIdx.x;
    float acc = 0.f;
#pragma unroll
    for (int c = 0; c < 8; c++) acc += d_part[(b * 8 + c) * Dn + d];
    out[b * Dn + d] = acc;
}

// ============================================================
extern "C" void kernel_launch(void* const* d_in, const int* in_sizes, int n_in,
                              void* d_out, int out_size) {
    const float* query = (const float*)d_in[0];
    const float* values = (const float*)d_in[1];
    const float* W1w = (const float*)d_in[2];
    const float* W1b = (const float*)d_in[3];
    const float* W2w = (const float*)d_in[4];
    const float* W2b = (const float*)d_in[5];
    const float* Vw  = (const float*)d_in[6];
    const float* Vb  = (const float*)d_in[7];
    float* out = (float*)d_out;

    qproj_kernel<<<Bn, 256>>>(query, W1w, W1b, W2b);
    score_kernel<<<(Bn * Tn) / 64, 256>>>(values, W2w, Vw, Vb);
    softmax_stats_kernel<<<Bn, 256>>>();
    weights_ctx_kernel<<<Bn * 8, 256>>>(values, out);
    reduce_ctx_kernel<<<Bn, 256>>>(out);
}

// round 3
// speedup vs baseline: 2.5441x; 2.5441x over previous
#include <cuda_runtime.h>
#include <math.h>
#include <stdint.h>

#define Bn 64
#define Tn 2048
#define Dn 256
#define Un 256

// ---- scratch (device globals, no allocation) ----
__device__ float d_qp[Bn * Un];            // q_proj + W1_b + W2_b
__device__ float d_score[Bn * Tn];         // pre-softmax scores
__device__ float d_maxv[Bn];
__device__ float d_den[Bn];
__device__ float d_part[Bn * 16 * Dn];     // partial context sums
__device__ float d_W2t[Un * Dn];           // W2 transposed: [u][d]

// ================= helpers =================
__device__ __forceinline__ uint32_t smem_u32(const void* p) {
    uint32_t a;
    asm("{ .reg .u64 t; cvta.to.shared.u64 t, %1; cvt.u32.u64 %0, t; }" : "=r"(a) : "l"(p));
    return a;
}
__device__ __forceinline__ void cp_async16(uint32_t dst, const void* src) {
    asm volatile("cp.async.ca.shared.global [%0], [%1], 16;" :: "r"(dst), "l"(src) : "memory");
}
__device__ __forceinline__ void cp_commit() {
    asm volatile("cp.async.commit_group;" ::: "memory");
}
template <int N>
__device__ __forceinline__ void cp_wait() {
    asm volatile("cp.async.wait_group %0;" :: "n"(N) : "memory");
}
__device__ __forceinline__ void mma_tf32(float* c, const uint32_t* a, const uint32_t* b) {
    asm volatile(
        "mma.sync.aligned.m16n8k8.row.col.f32.tf32.tf32.f32 "
        "{%0,%1,%2,%3}, {%4,%5,%6,%7}, {%8,%9}, {%0,%1,%2,%3};"
        : "+f"(c[0]), "+f"(c[1]), "+f"(c[2]), "+f"(c[3])
        : "r"(a[0]), "r"(a[1]), "r"(a[2]), "r"(a[3]), "r"(b[0]), "r"(b[1]));
}
static __device__ __forceinline__ float tanh_fast(float x) {
    float r;
    asm("tanh.approx.f32 %0, %1;" : "=f"(r) : "f"(x));
    return r;
}

// ============================================================
// Kernel 0: transpose W2 [D,U] -> d_W2t [U,D]
// ============================================================
__global__ void transpose_kernel(const float* __restrict__ W2w) {
    __shared__ float t[32][33];
    int bx = blockIdx.x * 32, by = blockIdx.y * 32;
    int x = threadIdx.x, y = threadIdx.y;  // 32x8
#pragma unroll
    for (int i = 0; i < 32; i += 8) t[y + i][x] = W2w[(by + y + i) * Un + bx + x];
    __syncthreads();
#pragma unroll
    for (int i = 0; i < 32; i += 8) d_W2t[(bx + y + i) * Dn + by + x] = t[x][y + i];
}

// ============================================================
// Kernel 1: q_proj[b][u] = query[b]@W1[:,u] + W1_b[u] + W2_b[u]
// ============================================================
__global__ void qproj_kernel(const float* __restrict__ query,
                             const float* __restrict__ W1w,
                             const float* __restrict__ W1b,
                             const float* __restrict__ W2b) {
    int b = blockIdx.x, u = threadIdx.x;
    __shared__ float qs[Dn];
    qs[u] = query[b * Dn + u];
    __syncthreads();
    float acc = 0.f;
#pragma unroll 8
    for (int d = 0; d < Dn; d++) acc = fmaf(qs[d], W1w[d * Un + u], acc);
    d_qp[b * Un + u] = acc + W1b[u] + W2b[u];
}

// ============================================================
// Kernel 2: mma.sync tf32 GEMM (64 x 256 x 256) + tanh + dot(Vw)
// 8 warps, each owns a 32-col slab (all 64 rows). K chunks of 32,
// cp.async double-buffered. Stride-36 smem -> conflict-free LDS.
// ============================================================
#define AS_STRIDE 36
#define AS_FLOATS (64 * AS_STRIDE)     // 2304 per buffer
#define BS_FLOATS (256 * AS_STRIDE)    // 9216 per buffer
#define SC_SMEM ((2 * AS_FLOATS + 2 * BS_FLOATS) * 4)   // 92160 B

__global__ __launch_bounds__(256)
void score_kernel(const float* __restrict__ values,
                  const float* __restrict__ Vw,
                  const float* __restrict__ Vb) {
    extern __shared__ __align__(16) char dsm[];
    float* Asf = (float*)dsm;                       // 2 x 2304
    float* Bsf = (float*)dsm + 2 * AS_FLOATS;       // 2 x 9216
    __shared__ float qs[Un];
    __shared__ float vs[Un];
    __shared__ float sp[64 * 8];

    const int tid = threadIdx.x;
    const int wid = tid >> 5;
    const int lane = tid & 31;
    const int g = lane >> 2;       // group id (fragment row / col)
    const int tg = lane & 3;       // thread-in-group
    const int r0 = blockIdx.x * 64;
    const int b = r0 >> 11;

    qs[tid] = d_qp[b * Un + tid];
    vs[tid] = Vw[tid];

    const uint32_t as_base = smem_u32(Asf);
    const uint32_t bs_base = smem_u32(Bsf);

    // ---- async chunk issue: A = values[r0..r0+63][kc..kc+31], B = W2t[0..255][kc..] ----
    auto issue_chunk = [&](int c, int buf) {
        const int kc = c * 32;
        const float* agp = values + (size_t)r0 * Dn + kc;
#pragma unroll
        for (int it = 0; it < 2; it++) {
            int s = tid + it * 256;          // 512 float4 slots
            int row = s >> 3, kq = s & 7;
            uint32_t dst = as_base + (buf * AS_FLOATS + row * AS_STRIDE + kq * 4) * 4;
            cp_async16(dst, agp + row * Dn + kq * 4);
        }
#pragma unroll
        for (int it = 0; it < 8; it++) {
            int s = tid + it * 256;          // 2048 float4 slots
            int row = s >> 3, kq = s & 7;
            uint32_t dst = bs_base + (buf * BS_FLOATS + row * AS_STRIDE + kq * 4) * 4;
            cp_async16(dst, d_W2t + row * Dn + kc + kq * 4);
        }
        cp_commit();
    };

    float acc[4][4][4];   // [m_tile][n_tile][c-frag]
#pragma unroll
    for (int i = 0; i < 4; i++)
#pragma unroll
        for (int j = 0; j < 4; j++)
#pragma unroll
            for (int q = 0; q < 4; q++) acc[i][j][q] = 0.f;

    issue_chunk(0, 0);

#pragma unroll 1
    for (int c = 0; c < 8; c++) {
        const int buf = c & 1;
        if (c < 7) issue_chunk(c + 1, buf ^ 1);
        if (c < 7) cp_wait<1>(); else cp_wait<0>();
        __syncthreads();   // chunk c resident for all threads

        const float* Ab = Asf + buf * AS_FLOATS;
        const float* Bb = Bsf + buf * BS_FLOATS;
        const uint32_t* Au = (const uint32_t*)Ab;
        const uint32_t* Bu = (const uint32_t*)Bb;

#pragma unroll
        for (int k8 = 0; k8 < 4; k8++) {
            const int kb = k8 * 8;
            uint32_t afr[4][4];
#pragma unroll
            for (int i = 0; i < 4; i++) {
                int row = i * 16 + g;
                afr[i][0] = Au[row * AS_STRIDE + kb + tg];
                afr[i][1] = Au[(row + 8) * AS_STRIDE + kb + tg];
                afr[i][2] = Au[row * AS_STRIDE + kb + tg + 4];
                afr[i][3] = Au[(row + 8) * AS_STRIDE + kb + tg + 4];
            }
            uint32_t bfr[4][2];
#pragma unroll
            for (int j = 0; j < 4; j++) {
                int urow = wid * 32 + j * 8 + g;
                bfr[j][0] = Bu[urow * AS_STRIDE + kb + tg];
                bfr[j][1] = Bu[urow * AS_STRIDE + kb + tg + 4];
            }
#pragma unroll
            for (int i = 0; i < 4; i++)
#pragma unroll
                for (int j = 0; j < 4; j++)
                    mma_tf32(acc[i][j], afr[i], bfr[j]);
        }
        __syncthreads();   // done reading buf before it is overwritten
    }

    // ---- epilogue: p[row] = sum_u tanh(acc + qs[u]) * vs[u] ----
    float p[4][2];
#pragma unroll
    for (int i = 0; i < 4; i++) { p[i][0] = 0.f; p[i][1] = 0.f; }

#pragma unroll
    for (int j = 0; j < 4; j++) {
        int u0 = wid * 32 + j * 8 + 2 * tg;
        int u1 = u0 + 1;
        float q0 = qs[u0], q1 = qs[u1], v0 = vs[u0], v1 = vs[u1];
#pragma unroll
        for (int i = 0; i < 4; i++) {
            p[i][0] = fmaf(tanh_fast(acc[i][j][0] + q0), v0, p[i][0]);
            p[i][0] = fmaf(tanh_fast(acc[i][j][1] + q1), v1, p[i][0]);
            p[i][1] = fmaf(tanh_fast(acc[i][j][2] + q0), v0, p[i][1]);
            p[i][1] = fmaf(tanh_fast(acc[i][j][3] + q1), v1, p[i][1]);
        }
    }
    // reduce over the 4 column-lanes (tg)
#pragma unroll
    for (int off = 1; off < 4; off <<= 1)
#pragma unroll
        for (int i = 0; i < 4; i++) {
            p[i][0] += __shfl_xor_sync(0xffffffffu, p[i][0], off);
            p[i][1] += __shfl_xor_sync(0xffffffffu, p[i][1], off);
        }
    if (tg == 0) {
#pragma unroll
        for (int i = 0; i < 4; i++) {
            sp[(i * 16 + g) * 8 + wid] = p[i][0];
            sp[(i * 16 + g + 8) * 8 + wid] = p[i][1];
        }
    }
    __syncthreads();
    if (tid < 64) {
        float s = 0.f;
#pragma unroll
        for (int w = 0; w < 8; w++) s += sp[tid * 8 + w];
        d_score[r0 + tid] = s + Vb[0];
    }
}

// ============================================================
// Kernel 3: per-b softmax stats
// ============================================================
__device__ __forceinline__ float warp_max(float v) {
#pragma unroll
    for (int o = 16; o > 0; o >>= 1) v = fmaxf(v, __shfl_xor_sync(0xffffffffu, v, o));
    return v;
}
__device__ __forceinline__ float warp_sum(float v) {
#pragma unroll
    for (int o = 16; o > 0; o >>= 1) v += __shfl_xor_sync(0xffffffffu, v, o);
    return v;
}

__global__ void softmax_stats_kernel() {
    int b = blockIdx.x, tid = threadIdx.x;
    __shared__ float red[8];
    __shared__ float bc;
    float m = -1e30f;
    for (int t = tid; t < Tn; t += 256) m = fmaxf(m, d_score[b * Tn + t]);
    m = warp_max(m);
    if ((tid & 31) == 0) red[tid >> 5] = m;
    __syncthreads();
    if (tid < 32) {
        float v = (tid < 8) ? red[tid] : -1e30f;
        v = warp_max(v);
        if (tid == 0) bc = v;
    }
    __syncthreads();
    float mv = bc;
    float s = 0.f;
    for (int t = tid; t < Tn; t += 256) s += expf(d_score[b * Tn + t] - mv);
    s = warp_sum(s);
    if ((tid & 31) == 0) red[tid >> 5] = s;
    __syncthreads();
    if (tid < 32) {
        float v = (tid < 8) ? red[tid] : 0.f;
        v = warp_sum(v);
        if (tid == 0) { d_maxv[b] = mv; d_den[b] = v; }
    }
}

// ============================================================
// Kernel 4: weights + partial context (grid = B*16, 128-t chunks)
// ============================================================
__global__ void weights_ctx_kernel(const float* __restrict__ values,
                                   float* __restrict__ out) {
    int b = blockIdx.x >> 4;
    int ch = blockIdx.x & 15;
    int tid = threadIdx.x;
    __shared__ float sw[128];
    if (tid < 128) {
        int t = ch * 128 + tid;
        float w = expf(d_score[b * Tn + t] - d_maxv[b]) / d_den[b];
        out[Bn * Dn + b * Tn + t] = w;
        sw[tid] = w;
    }
    __syncthreads();
    float acc = 0.f;
    const float* vp = values + ((size_t)(b * Tn + ch * 128)) * Dn + tid;
#pragma unroll 8
    for (int tt = 0; tt < 128; tt++) acc = fmaf(sw[tt], vp[(size_t)tt * Dn], acc);
    d_part[(b * 16 + ch) * Dn + tid] = acc;
}

// ============================================================
// Kernel 5: reduce partial contexts -> context_vector
// ============================================================
__global__ void reduce_ctx_kernel(float* __restrict__ out) {
    int b = blockIdx.x, d = threadIdx.x;
    float acc = 0.f;
#pragma unroll
    for (int c = 0; c < 16; c++) acc += d_part[(b * 16 + c) * Dn + d];
    out[b * Dn + d] = acc;
}

// ============================================================
extern "C" void kernel_launch(void* const* d_in, const int* in_sizes, int n_in,
                              void* d_out, int out_size) {
    const float* query = (const float*)d_in[0];
    const float* values = (const float*)d_in[1];
    const float* W1w = (const float*)d_in[2];
    const float* W1b = (const float*)d_in[3];
    const float* W2w = (const float*)d_in[4];
    const float* W2b = (const float*)d_in[5];
    const float* Vw  = (const float*)d_in[6];
    const float* Vb  = (const float*)d_in[7];
    float* out = (float*)d_out;

    static int smem_set = 0;
    if (!smem_set) {
        cudaFuncSetAttribute(score_kernel, cudaFuncAttributeMaxDynamicSharedMemorySize, SC_SMEM);
        smem_set = 1;
    }

    transpose_kernel<<<dim3(8, 8), dim3(32, 8)>>>(W2w);
    qproj_kernel<<<Bn, 256>>>(query, W1w, W1b, W2b);
    score_kernel<<<(Bn * Tn) / 64, 256, SC_SMEM>>>(values, Vw, Vb);
    softmax_stats_kernel<<<Bn, 256>>>();
    weights_ctx_kernel<<<Bn * 16, 256>>>(values, out);
    reduce_ctx_kernel<<<Bn, 256>>>(out);
}

// round 4
// speedup vs baseline: 2.6992x; 1.0609x over previous
#include <cuda_runtime.h>
#include <math.h>
#include <stdint.h>

#define Bn 64
#define Tn 2048
#define Dn 256
#define Un 256

// ---- scratch (device globals, no allocation) ----
__device__ float d_qp[Bn * Un];            // q_proj + W1_b + W2_b
__device__ float d_score[Bn * Tn];         // pre-softmax scores
__device__ float d_maxv[Bn];
__device__ float d_den[Bn];
__device__ float d_part[Bn * 16 * Dn];     // partial context sums
__device__ float d_W2t[Un * Dn];           // W2 transposed: [u][d]

// ================= helpers =================
__device__ __forceinline__ uint32_t smem_u32(const void* p) {
    uint32_t a;
    asm("{ .reg .u64 t; cvta.to.shared.u64 t, %1; cvt.u32.u64 %0, t; }" : "=r"(a) : "l"(p));
    return a;
}
__device__ __forceinline__ void cp_async16(uint32_t dst, const void* src) {
    asm volatile("cp.async.ca.shared.global [%0], [%1], 16;" :: "r"(dst), "l"(src) : "memory");
}
__device__ __forceinline__ void cp_commit() {
    asm volatile("cp.async.commit_group;" ::: "memory");
}
template <int N>
__device__ __forceinline__ void cp_wait() {
    asm volatile("cp.async.wait_group %0;" :: "n"(N) : "memory");
}
__device__ __forceinline__ void mma_tf32(float* c, const uint32_t* a, uint32_t b0, uint32_t b1) {
    asm volatile(
        "mma.sync.aligned.m16n8k8.row.col.f32.tf32.tf32.f32 "
        "{%0,%1,%2,%3}, {%4,%5,%6,%7}, {%8,%9}, {%0,%1,%2,%3};"
        : "+f"(c[0]), "+f"(c[1]), "+f"(c[2]), "+f"(c[3])
        : "r"(a[0]), "r"(a[1]), "r"(a[2]), "r"(a[3]), "r"(b0), "r"(b1));
}
static __device__ __forceinline__ float tanh_fast(float x) {
    float r;
    asm("tanh.approx.f32 %0, %1;" : "=f"(r) : "f"(x));
    return r;
}

// ============================================================
// Kernel 0: prep — qproj (blocks 0..63) + W2 transpose (blocks 64..127)
// ============================================================
__global__ void prep_kernel(const float* __restrict__ query,
                            const float* __restrict__ W1w,
                            const float* __restrict__ W1b,
                            const float* __restrict__ W2w,
                            const float* __restrict__ W2b) {
    if (blockIdx.x < 64) {
        int b = blockIdx.x, u = threadIdx.x;
        __shared__ float qs[Dn];
        qs[u] = query[b * Dn + u];
        __syncthreads();
        float acc = 0.f;
#pragma unroll 8
        for (int d = 0; d < Dn; d++) acc = fmaf(qs[d], W1w[d * Un + u], acc);
        d_qp[b * Un + u] = acc + W1b[u] + W2b[u];
    } else {
        __shared__ float t[32][33];
        int tile = blockIdx.x - 64;
        int bx = (tile & 7) * 32, by = (tile >> 3) * 32;
        int x = threadIdx.x & 31, y = threadIdx.x >> 5;  // 32x8
#pragma unroll
        for (int i = 0; i < 32; i += 8) t[y + i][x] = W2w[(by + y + i) * Un + bx + x];
        __syncthreads();
#pragma unroll
        for (int i = 0; i < 32; i += 8) d_W2t[(bx + y + i) * Dn + by + x] = t[x][y + i];
    }
}

// ============================================================
// Kernel 2: mma.sync tf32 GEMM (128 x 256 x 256) + tanh + dot(Vw)
// 8 warps = 2 M-groups x 4 N-groups; each warp 64 rows x 64 cols.
// K chunks of 32, cp.async double-buffered, stride-36 smem.
// ============================================================
#define AS_STRIDE 36
#define A_ROWS 128
#define AS_FLOATS (A_ROWS * AS_STRIDE)   // 4608 per buffer
#define BS_FLOATS (256 * AS_STRIDE)      // 9216 per buffer
#define SC_SMEM ((2 * AS_FLOATS + 2 * BS_FLOATS) * 4)   // 110592 B

__global__ __launch_bounds__(256, 1)
void score_kernel(const float* __restrict__ values,
                  const float* __restrict__ Vw,
                  const float* __restrict__ Vb) {
    extern __shared__ __align__(16) char dsm[];
    float* Asf = (float*)dsm;                       // 2 x 4608
    float* Bsf = (float*)dsm + 2 * AS_FLOATS;       // 2 x 9216
    __shared__ float qs[Un];
    __shared__ float vs[Un];
    __shared__ float sp[A_ROWS * 4];

    const int tid = threadIdx.x;
    const int wid = tid >> 5;
    const int lane = tid & 31;
    const int g = lane >> 2;       // 0..7
    const int tg = lane & 3;       // 0..3
    const int mw = wid >> 2;       // 0..1  (row half)
    const int nw = wid & 3;        // 0..3  (col quarter)
    const int r0 = blockIdx.x * A_ROWS;
    const int b = r0 >> 11;

    qs[tid] = d_qp[b * Un + tid];
    vs[tid] = Vw[tid];

    const uint32_t as_base = smem_u32(Asf);
    const uint32_t bs_base = smem_u32(Bsf);

    auto issue_chunk = [&](int c, int buf) {
        const int kc = c * 32;
        const float* agp = values + (size_t)r0 * Dn + kc;
#pragma unroll
        for (int it = 0; it < 4; it++) {
            int s = tid + it * 256;          // 1024 float4 slots
            int row = s >> 3, kq = s & 7;
            uint32_t dst = as_base + (buf * AS_FLOATS + row * AS_STRIDE + kq * 4) * 4;
            cp_async16(dst, agp + row * Dn + kq * 4);
        }
#pragma unroll
        for (int it = 0; it < 8; it++) {
            int s = tid + it * 256;          // 2048 float4 slots
            int row = s >> 3, kq = s & 7;
            uint32_t dst = bs_base + (buf * BS_FLOATS + row * AS_STRIDE + kq * 4) * 4;
            cp_async16(dst, d_W2t + row * Dn + kc + kq * 4);
        }
        cp_commit();
    };

    float acc[4][8][4];   // [m_tile][n_tile][c-frag] = 128 regs
#pragma unroll
    for (int i = 0; i < 4; i++)
#pragma unroll
        for (int j = 0; j < 8; j++)
#pragma unroll
            for (int q = 0; q < 4; q++) acc[i][j][q] = 0.f;

    issue_chunk(0, 0);

#pragma unroll 1
    for (int c = 0; c < 8; c++) {
        const int buf = c & 1;
        if (c < 7) issue_chunk(c + 1, buf ^ 1);
        if (c < 7) cp_wait<1>(); else cp_wait<0>();
        __syncthreads();

        const uint32_t* Au = (const uint32_t*)(Asf + buf * AS_FLOATS);
        const uint32_t* Bu = (const uint32_t*)(Bsf + buf * BS_FLOATS);

#pragma unroll
        for (int k8 = 0; k8 < 4; k8++) {
            const int kb = k8 * 8;
            uint32_t afr[4][4];
#pragma unroll
            for (int i = 0; i < 4; i++) {
                int row = mw * 64 + i * 16 + g;
                afr[i][0] = Au[row * AS_STRIDE + kb + tg];
                afr[i][1] = Au[(row + 8) * AS_STRIDE + kb + tg];
                afr[i][2] = Au[row * AS_STRIDE + kb + tg + 4];
                afr[i][3] = Au[(row + 8) * AS_STRIDE + kb + tg + 4];
            }
#pragma unroll
            for (int j = 0; j < 8; j++) {
                int urow = nw * 64 + j * 8 + g;
                uint32_t b0 = Bu[urow * AS_STRIDE + kb + tg];
                uint32_t b1 = Bu[urow * AS_STRIDE + kb + tg + 4];
#pragma unroll
                for (int i = 0; i < 4; i++)
                    mma_tf32(acc[i][j], afr[i], b0, b1);
            }
        }
        __syncthreads();
    }

    // ---- epilogue: p[row] = sum_u tanh(acc + qs[u]) * vs[u] ----
    float p[4][2];
#pragma unroll
    for (int i = 0; i < 4; i++) { p[i][0] = 0.f; p[i][1] = 0.f; }

#pragma unroll
    for (int j = 0; j < 8; j++) {
        int u0 = nw * 64 + j * 8 + 2 * tg;
        int u1 = u0 + 1;
        float q0 = qs[u0], q1 = qs[u1], v0 = vs[u0], v1 = vs[u1];
#pragma unroll
        for (int i = 0; i < 4; i++) {
            p[i][0] = fmaf(tanh_fast(acc[i][j][0] + q0), v0, p[i][0]);
            p[i][0] = fmaf(tanh_fast(acc[i][j][1] + q1), v1, p[i][0]);
            p[i][1] = fmaf(tanh_fast(acc[i][j][2] + q0), v0, p[i][1]);
            p[i][1] = fmaf(tanh_fast(acc[i][j][3] + q1), v1, p[i][1]);
        }
    }
#pragma unroll
    for (int off = 1; off < 4; off <<= 1)
#pragma unroll
        for (int i = 0; i < 4; i++) {
            p[i][0] += __shfl_xor_sync(0xffffffffu, p[i][0], off);
            p[i][1] += __shfl_xor_sync(0xffffffffu, p[i][1], off);
        }
    if (tg == 0) {
#pragma unroll
        for (int i = 0; i < 4; i++) {
            sp[(mw * 64 + i * 16 + g) * 4 + nw] = p[i][0];
            sp[(mw * 64 + i * 16 + g + 8) * 4 + nw] = p[i][1];
        }
    }
    __syncthreads();
    if (tid < A_ROWS) {
        float s = sp[tid * 4] + sp[tid * 4 + 1] + sp[tid * 4 + 2] + sp[tid * 4 + 3];
        d_score[r0 + tid] = s + Vb[0];
    }
}

// ============================================================
// Kernel 3: per-b softmax stats (512 threads)
// ============================================================
__device__ __forceinline__ float warp_max(float v) {
#pragma unroll
    for (int o = 16; o > 0; o >>= 1) v = fmaxf(v, __shfl_xor_sync(0xffffffffu, v, o));
    return v;
}
__device__ __forceinline__ float warp_sum(float v) {
#pragma unroll
    for (int o = 16; o > 0; o >>= 1) v += __shfl_xor_sync(0xffffffffu, v, o);
    return v;
}

__global__ void softmax_stats_kernel() {
    int b = blockIdx.x, tid = threadIdx.x;
    __shared__ float red[16];
    __shared__ float bc;
    float m = -1e30f;
    for (int t = tid; t < Tn; t += 512) m = fmaxf(m, d_score[b * Tn + t]);
    m = warp_max(m);
    if ((tid & 31) == 0) red[tid >> 5] = m;
    __syncthreads();
    if (tid < 32) {
        float v = (tid < 16) ? red[tid] : -1e30f;
        v = warp_max(v);
        if (tid == 0) bc = v;
    }
    __syncthreads();
    float mv = bc;
    float s = 0.f;
    for (int t = tid; t < Tn; t += 512) s += expf(d_score[b * Tn + t] - mv);
    s = warp_sum(s);
    if ((tid & 31) == 0) red[tid >> 5] = s;
    __syncthreads();
    if (tid < 32) {
        float v = (tid < 16) ? red[tid] : 0.f;
        v = warp_sum(v);
        if (tid == 0) { d_maxv[b] = mv; d_den[b] = v; }
    }
}

// ============================================================
// Kernel 4: weights + partial context (grid = B*16, 128-t chunks)
// thread = (row_group rg 0..3) x (d-quad dg 0..63), float4 loads
// ============================================================
__global__ void weights_ctx_kernel(const float* __restrict__ values,
                                   float* __restrict__ out) {
    int b = blockIdx.x >> 4;
    int ch = blockIdx.x & 15;
    int tid = threadIdx.x;
    __shared__ float sw[128];
    __shared__ float4 red[256];

    if (tid < 128) {
        int t = ch * 128 + tid;
        float w = expf(d_score[b * Tn + t] - d_maxv[b]) / d_den[b];
        out[Bn * Dn + b * Tn + t] = w;
        sw[tid] = w;
    }
    __syncthreads();

    int rg = tid >> 6, dg = tid & 63;
    const float4* vp = (const float4*)(values + (size_t)(b * Tn + ch * 128 + rg * 32) * Dn) + dg;
    float4 acc = make_float4(0.f, 0.f, 0.f, 0.f);
#pragma unroll 8
    for (int tt = 0; tt < 32; tt++) {
        float w = sw[rg * 32 + tt];
        float4 v = vp[(size_t)tt * 64];
        acc.x = fmaf(w, v.x, acc.x);
        acc.y = fmaf(w, v.y, acc.y);
        acc.z = fmaf(w, v.z, acc.z);
        acc.w = fmaf(w, v.w, acc.w);
    }
    red[tid] = acc;
    __syncthreads();
    if (tid < 64) {
        float4 a = red[tid], b1 = red[64 + tid], c = red[128 + tid], d = red[192 + tid];
        a.x += b1.x + c.x + d.x;
        a.y += b1.y + c.y + d.y;
        a.z += b1.z + c.z + d.z;
        a.w += b1.w + c.w + d.w;
        ((float4*)(d_part + (b * 16 + ch) * Dn))[tid] = a;
    }
}

// ============================================================
// Kernel 5: reduce partial contexts -> context_vector
// ============================================================
__global__ void reduce_ctx_kernel(float* __restrict__ out) {
    int b = blockIdx.x, d = threadIdx.x;
    float acc = 0.f;
#pragma unroll
    for (int c = 0; c < 16; c++) acc += d_part[(b * 16 + c) * Dn + d];
    out[b * Dn + d] = acc;
}

// ============================================================
extern "C" void kernel_launch(void* const* d_in, const int* in_sizes, int n_in,
                              void* d_out, int out_size) {
    const float* query = (const float*)d_in[0];
    const float* values = (const float*)d_in[1];
    const float* W1w = (const float*)d_in[2];
    const float* W1b = (const float*)d_in[3];
    const float* W2w = (const float*)d_in[4];
    const float* W2b = (const float*)d_in[5];
    const float* Vw  = (const float*)d_in[6];
    const float* Vb  = (const float*)d_in[7];
    float* out = (float*)d_out;

    static int smem_set = 0;
    if (!smem_set) {
        cudaFuncSetAttribute(score_kernel, cudaFuncAttributeMaxDynamicSharedMemorySize, SC_SMEM);
        smem_set = 1;
    }

    prep_kernel<<<128, 256>>>(query, W1w, W1b, W2w, W2b);
    score_kernel<<<(Bn * Tn) / A_ROWS, 256, SC_SMEM>>>(values, Vw, Vb);
    softmax_stats_kernel<<<Bn, 512>>>();
    weights_ctx_kernel<<<Bn * 16, 256>>>(values, out);
    reduce_ctx_kernel<<<Bn, 256>>>(out);
}